// round 15
// baseline (speedup 1.0000x reference)
#include <cuda_runtime.h>
#include <cuda_fp16.h>
#include <cstdint>

// Shapes (fixed): B=4, N=8, M=64, F=128, D=128
#define BN_TOT 32
#define M_DIM  64
#define F_DIM  128
#define D_DIM  128
#define EPS_LN 1e-5f

// C scratch: [bn][chunk0..2][64 rows][128] fp32.
__device__ float g_C[BN_TOT * 5 * M_DIM * F_DIM];
// colmeans: [bn][0:R-term (chunk3), 1:P-term (chunk4)][128]
__device__ float g_means[BN_TOT * 2 * F_DIM];
// fp16 W2 slab (single term), swizzled layout, 32 KB.
__device__ __align__(16) unsigned char g_wsl[32768];
// Precomputed LN stats per (bn,i,j): {mu, rstd}.
__device__ float2 g_musig[BN_TOT * M_DIM * M_DIM];

// ---------------------------------------------------------------------------
// Helpers
// ---------------------------------------------------------------------------
static __device__ __forceinline__ uint32_t cvta_smem(const void* p) {
    uint32_t a;
    asm("{ .reg .u64 t; cvta.to.shared.u64 t, %1; cvt.u32.u64 %0, t; }"
        : "=r"(a) : "l"(p));
    return a;
}
static __device__ __forceinline__ uint32_t packbf(float lo, float hi) {
    uint32_t r;
    asm("cvt.rn.bf16x2.f32 %0, %1, %2;" : "=r"(r) : "f"(hi), "f"(lo));
    return r;
}
static __device__ __forceinline__ uint32_t swz(uint32_t row, uint32_t kbyte) {
    return row * 256u + ((((kbyte >> 4) ^ (row & 7u)) << 4) | (kbyte & 15u));
}
static __device__ __forceinline__ void ldsm4(uint32_t* r, uint32_t addr) {
    asm volatile("ldmatrix.sync.aligned.m8n8.x4.shared.b16 {%0,%1,%2,%3}, [%4];"
                 : "=r"(r[0]), "=r"(r[1]), "=r"(r[2]), "=r"(r[3]) : "r"(addr));
}
// bf16 mma (stage1)
static __device__ __forceinline__ void mma16816(float* c, const uint32_t* a,
                                                uint32_t b0, uint32_t b1) {
    asm volatile(
        "mma.sync.aligned.m16n8k16.row.col.f32.bf16.bf16.f32 "
        "{%0,%1,%2,%3}, {%4,%5,%6,%7}, {%8,%9}, {%0,%1,%2,%3};"
        : "+f"(c[0]), "+f"(c[1]), "+f"(c[2]), "+f"(c[3])
        : "r"(a[0]), "r"(a[1]), "r"(a[2]), "r"(a[3]), "r"(b0), "r"(b1));
}
// fp16 mma (stage2)
static __device__ __forceinline__ void mma16816h(float* c, const uint32_t* a,
                                                 uint32_t b0, uint32_t b1) {
    asm volatile(
        "mma.sync.aligned.m16n8k16.row.col.f32.f16.f16.f32 "
        "{%0,%1,%2,%3}, {%4,%5,%6,%7}, {%8,%9}, {%0,%1,%2,%3};"
        : "+f"(c[0]), "+f"(c[1]), "+f"(c[2]), "+f"(c[3])
        : "r"(a[0]), "r"(a[1]), "r"(a[2]), "r"(a[3]), "r"(b0), "r"(b1));
}
static __device__ __forceinline__ void cp_async16(uint32_t dst, const void* gp) {
    uint64_t g;
    asm("cvta.to.global.u64 %0, %1;" : "=l"(g) : "l"(gp));
    asm volatile("cp.async.cg.shared.global [%0], [%1], 16;"
                 :: "r"(dst), "l"(g) : "memory");
}
// bf16 hi/lo split (stage1)
static __device__ __forceinline__ void split4(const float4& v, uint2& hi, uint2& lo) {
    const uint32_t hiA = packbf(v.x, v.y);
    const uint32_t hiB = packbf(v.z, v.w);
    const float r0 = v.x - __uint_as_float(hiA << 16);
    const float r1 = v.y - __uint_as_float(hiA & 0xffff0000u);
    const float r2 = v.z - __uint_as_float(hiB << 16);
    const float r3 = v.w - __uint_as_float(hiB & 0xffff0000u);
    hi = make_uint2(hiA, hiB);
    lo = make_uint2(packbf(r0, r1), packbf(r2, r3));
}
static __device__ __forceinline__ uint32_t h2u(__half2 h) {
    return *reinterpret_cast<uint32_t*>(&h);
}
static __device__ __forceinline__ uint2 packhf4(float a, float b, float c, float d) {
    return make_uint2(h2u(__floats2half2_rn(a, b)), h2u(__floats2half2_rn(c, d)));
}

// ---------------------------------------------------------------------------
// Stage 1: grid (32, 4). chunk<3: bf16 3-term MMA C_chunk = x . W1chunk^T.
// chunk==3: light path — mean(x), coalesced smem-staged projections.
// ---------------------------------------------------------------------------
#define S1_AHI 0
#define S1_ALO 16384
#define S1_BHI 32768
#define S1_BLO 65536
#define SMEM1_BYTES 98304
#define WST 132

__global__ void __launch_bounds__(256, 2)
hoe_stage1mm(const float* __restrict__ x, const float* __restrict__ W1) {
    extern __shared__ char smem[];
    const uint32_t sbase = cvta_smem(smem);
    const int tid  = threadIdx.x;
    const int lane = tid & 31;
    const int wid  = tid >> 5;
    const int bn    = blockIdx.x;
    const int chunk = blockIdx.y;

    if (chunk == 3) {
        float* wbuf   = (float*)smem;            // [128][WST]
        float* mean_s = wbuf + 128 * WST;        // 128
        float* part   = mean_s + 128;            // 256
        const float* xb = x + bn * (M_DIM * F_DIM);
        const int f = tid & 127, half = tid >> 7;
        float s = 0.f;
        #pragma unroll 8
        for (int i2 = half * 32; i2 < half * 32 + 32; i2++)
            s += __ldg(xb + i2 * F_DIM + f);
        part[tid] = s;
        __syncthreads();
        if (tid < 128) mean_s[tid] = (part[tid] + part[tid + 128]) * (1.0f / 64.0f);

        #pragma unroll
        for (int sel = 0; sel < 2; sel++) {
            __syncthreads();
            #pragma unroll
            for (int it = 0; it < 16; it++) {
                const int idx = it * 256 + tid;
                const int r = idx >> 5, cw = idx & 31;
                *(float4*)&wbuf[r * WST + cw * 4] =
                    __ldg((const float4*)(W1 + r * 640 + 384 + sel * 128 + cw * 4));
            }
            __syncthreads();
            if (tid < 128) {
                const float* wr = wbuf + tid * WST;
                float a0 = 0.f, a1 = 0.f, a2 = 0.f, a3 = 0.f;
                #pragma unroll 8
                for (int k = 0; k < 128; k += 4) {
                    a0 = fmaf(mean_s[k + 0], wr[k + 0], a0);
                    a1 = fmaf(mean_s[k + 1], wr[k + 1], a1);
                    a2 = fmaf(mean_s[k + 2], wr[k + 2], a2);
                    a3 = fmaf(mean_s[k + 3], wr[k + 3], a3);
                }
                g_means[(bn * 2 + sel) * F_DIM + tid] = (a0 + a1) + (a2 + a3);
            }
        }
        return;
    }

    #pragma unroll
    for (int it = 0; it < 16; it++) {
        const int idx = it * 256 + tid;
        const int r  = idx >> 5;
        const int cw = idx & 31;
        uint2 hi, lo;
        split4(__ldg((const float4*)(W1 + r * 640 + chunk * 128 + cw * 4)), hi, lo);
        const uint32_t off = swz((uint32_t)r, (uint32_t)cw * 8u);
        *(uint2*)(smem + S1_BHI + off) = hi;
        *(uint2*)(smem + S1_BLO + off) = lo;
    }
    const float4* xb = (const float4*)(x + bn * (M_DIM * F_DIM));
    #pragma unroll
    for (int it = 0; it < 8; it++) {
        const int e   = it * 256 + tid;
        const int row = e >> 5;
        const int cw  = e & 31;
        uint2 hi, lo;
        split4(__ldg(xb + e), hi, lo);
        const uint32_t off = swz((uint32_t)row, (uint32_t)cw * 8u);
        *(uint2*)(smem + S1_AHI + off) = hi;
        *(uint2*)(smem + S1_ALO + off) = lo;
    }
    __syncthreads();

    const int warpM = wid >> 2;
    const int warpN = wid & 3;
    const int q  = lane >> 3;
    const int lr = lane & 7;
    const int rowA  = lr + ((q & 1) << 3);
    const int cselA = q >> 1;
    uint32_t rowOffA[2];
    #pragma unroll
    for (int mt = 0; mt < 2; mt++)
        rowOffA[mt] = (uint32_t)(warpM * 32 + mt * 16 + rowA) * 256u;
    const int rowB  = lr + ((q >> 1) << 3);
    const int cselB = q & 1;
    uint32_t rowOffB[2];
    #pragma unroll
    for (int np = 0; np < 2; np++)
        rowOffB[np] = (uint32_t)(warpN * 32 + np * 16 + rowB) * 256u;

    float acc[2][4][4];
    #pragma unroll
    for (int mt = 0; mt < 2; mt++)
        #pragma unroll
        for (int nt = 0; nt < 4; nt++)
            #pragma unroll
            for (int e = 0; e < 4; e++) acc[mt][nt][e] = 0.f;

    #pragma unroll
    for (int kk = 0; kk < 8; kk++) {
        const uint32_t kxA = (uint32_t)(((kk << 1) + cselA) ^ lr) << 4;
        const uint32_t kxB = (uint32_t)(((kk << 1) + cselB) ^ lr) << 4;
        uint32_t ah[2][4], al[2][4], bh[2][4], bl[2][4];
        #pragma unroll
        for (int mt = 0; mt < 2; mt++) {
            ldsm4(ah[mt], sbase + S1_AHI + rowOffA[mt] + kxA);
            ldsm4(al[mt], sbase + S1_ALO + rowOffA[mt] + kxA);
        }
        #pragma unroll
        for (int np = 0; np < 2; np++) {
            ldsm4(bh[np], sbase + S1_BHI + rowOffB[np] + kxB);
            ldsm4(bl[np], sbase + S1_BLO + rowOffB[np] + kxB);
        }
        #pragma unroll
        for (int mt = 0; mt < 2; mt++)
            #pragma unroll
            for (int nt = 0; nt < 4; nt++) {
                const int np = nt >> 1;
                const int hb = (nt & 1) << 1;
                mma16816(acc[mt][nt], ah[mt], bh[np][hb], bh[np][hb + 1]);
                mma16816(acc[mt][nt], al[mt], bh[np][hb], bh[np][hb + 1]);
                mma16816(acc[mt][nt], ah[mt], bl[np][hb], bl[np][hb + 1]);
            }
    }

    float* cb = g_C + ((bn * 5 + chunk) * M_DIM) * F_DIM;
    #pragma unroll
    for (int mt = 0; mt < 2; mt++)
        #pragma unroll
        for (int half = 0; half < 2; half++) {
            const int m = warpM * 32 + mt * 16 + (lane >> 2) + half * 8;
            #pragma unroll
            for (int nt = 0; nt < 4; nt++) {
                const int n = warpN * 32 + nt * 8 + (lane & 3) * 2;
                *(float2*)(cb + m * 128 + n) =
                    make_float2(acc[mt][nt][half * 2], acc[mt][nt][half * 2 + 1]);
            }
        }
}

// ---------------------------------------------------------------------------
// Stats (+ fp16 W2 prep folded in): grid (32 bn, 4 j-slices) = 128 blocks.
// Cross-GEMM mapping: i in {lane, lane+32} (4-way conflicts), jj in
// {warp, warp+8} (broadcast, conflict-free).
// ---------------------------------------------------------------------------
#define PST 132
#define STATS_SMEM ((64 * PST + 16 * PST + 160) * 4)

__global__ void __launch_bounds__(256, 1)
hoe_stats(const float* __restrict__ b1, const float* __restrict__ W2) {
    extern __shared__ float sf[];
    float* Ps   = sf;                  // [64][PST]
    float* Qs   = Ps + 64 * PST;       // [16][PST]
    float* sumP = Qs + 16 * PST;       // 64
    float* sqP  = sumP + 64;           // 64
    float* sumQ = sqP + 64;            // 16
    float* sqQ  = sumQ + 16;           // 16

    const int bn  = blockIdx.x;
    const int j0  = blockIdx.y * 16;
    const int tid = threadIdx.x;

    // --- folded W2 prep (single fp16 term) ---
    {
        const int lb = blockIdx.x * 4 + blockIdx.y;
        if (tid < 32) {
            const int idx = lb * 32 + tid;        // < 4096
            const int r = idx >> 5, cw = idx & 31;
            const float4 v = __ldg((const float4*)(W2 + r * 128 + cw * 4));
            const uint32_t off = swz((uint32_t)r, (uint32_t)cw * 8u);
            *(uint2*)(g_wsl + off) = packhf4(v.x, v.y, v.z, v.w);
        }
    }

    const float* C0 = g_C + ((bn * 5 + 0) * M_DIM) * F_DIM;
    const float* C1 = g_C + ((bn * 5 + 1) * M_DIM) * F_DIM;
    const float* C2 = g_C + ((bn * 5 + 2) * M_DIM) * F_DIM;
    const float* mR = g_means + (bn * 2 + 0) * F_DIM;
    const float* mP = g_means + (bn * 2 + 1) * F_DIM;

    #pragma unroll
    for (int it = 0; it < 8; it++) {
        const int e = it * 256 + tid;
        const int i = e >> 5;
        const int f = (e & 31) * 4;
        float4 p = __ldg((const float4*)(C1 + i * 128 + f));
        const float4 mp = __ldg((const float4*)(mP + f));
        const float4 bb = __ldg((const float4*)(b1 + f));
        p.x += mp.x + bb.x; p.y += mp.y + bb.y;
        p.z += mp.z + bb.z; p.w += mp.w + bb.w;
        *(float4*)&Ps[i * PST + f] = p;
    }
    #pragma unroll
    for (int it = 0; it < 2; it++) {
        const int e = it * 256 + tid;
        const int jj = e >> 5;
        const int f  = (e & 31) * 4;
        *(float4*)&Qs[jj * PST + f] = __ldg((const float4*)(C2 + (j0 + jj) * 128 + f));
    }
    __syncthreads();

    {
        const int i = tid >> 2, part = tid & 3;
        float s = 0.f, ss = 0.f;
        #pragma unroll
        for (int f = part * 32; f < part * 32 + 32; f += 4) {
            const float4 p = *(const float4*)&Ps[i * PST + f];
            s += p.x + p.y + p.z + p.w;
            ss += p.x * p.x + p.y * p.y + p.z * p.z + p.w * p.w;
        }
        s  += __shfl_xor_sync(0xffffffffu, s, 1);  s  += __shfl_xor_sync(0xffffffffu, s, 2);
        ss += __shfl_xor_sync(0xffffffffu, ss, 1); ss += __shfl_xor_sync(0xffffffffu, ss, 2);
        if (part == 0) { sumP[i] = s; sqP[i] = ss; }
    }
    if (tid < 64) {
        const int jj = tid >> 2, part = tid & 3;
        float s = 0.f, ss = 0.f;
        #pragma unroll
        for (int f = part * 32; f < part * 32 + 32; f += 4) {
            const float4 p = *(const float4*)&Qs[jj * PST + f];
            s += p.x + p.y + p.z + p.w;
            ss += p.x * p.x + p.y * p.y + p.z * p.z + p.w * p.w;
        }
        s  += __shfl_xor_sync(0xffffffffu, s, 1);  s  += __shfl_xor_sync(0xffffffffu, s, 2);
        ss += __shfl_xor_sync(0xffffffffu, ss, 1); ss += __shfl_xor_sync(0xffffffffu, ss, 2);
        if (part == 0) { sumQ[jj] = s; sqQ[jj] = ss; }
    }
    __syncthreads();

    {
        const int lane = tid & 31;
        const int wq   = tid >> 5;      // 0..7
        // cells: i in {lane, lane+32}, jj in {wq, wq+8}
        float a00 = 0, a01 = 0, a10 = 0, a11 = 0;
        #pragma unroll 8
        for (int f = 0; f < 128; f += 4) {
            const float4 p0 = *(const float4*)&Ps[lane * PST + f];
            const float4 p1 = *(const float4*)&Ps[(lane + 32) * PST + f];
            const float4 q0 = *(const float4*)&Qs[wq * PST + f];
            const float4 q1 = *(const float4*)&Qs[(wq + 8) * PST + f];
            a00 = fmaf(p0.x, q0.x, a00); a00 = fmaf(p0.y, q0.y, a00);
            a00 = fmaf(p0.z, q0.z, a00); a00 = fmaf(p0.w, q0.w, a00);
            a01 = fmaf(p0.x, q1.x, a01); a01 = fmaf(p0.y, q1.y, a01);
            a01 = fmaf(p0.z, q1.z, a01); a01 = fmaf(p0.w, q1.w, a01);
            a10 = fmaf(p1.x, q0.x, a10); a10 = fmaf(p1.y, q0.y, a10);
            a10 = fmaf(p1.z, q0.z, a10); a10 = fmaf(p1.w, q0.w, a10);
            a11 = fmaf(p1.x, q1.x, a11); a11 = fmaf(p1.y, q1.y, a11);
            a11 = fmaf(p1.z, q1.z, a11); a11 = fmaf(p1.w, q1.w, a11);
        }
        const float cr[2][2] = { { a00, a01 }, { a10, a11 } };
        #pragma unroll
        for (int a = 0; a < 2; a++) {
            const int i = lane + a * 32;
            #pragma unroll
            for (int b = 0; b < 2; b++) {
                const int jj = wq + b * 8;
                const int j  = j0 + jj;
                if (i == j) continue;
                const float s   = sumP[i] + sumQ[jj];
                const float ss  = sqP[i] + 2.f * cr[a][b] + sqQ[jj];
                const float mu  = s * (1.0f / F_DIM);
                const float var = ss * (1.0f / F_DIM) - mu * mu;
                g_musig[(bn * 64 + i) * 64 + j] = make_float2(mu, rsqrtf(var + EPS_LN));
            }
        }
    }

    if (tid < 16) {
        const int i = j0 + tid;
        float s = 0.f, ss = 0.f;
        #pragma unroll 8
        for (int f = 0; f < 128; f += 4) {
            const float4 r  = __ldg((const float4*)(C0 + i * 128 + f));
            const float4 mr = __ldg((const float4*)(mR + f));
            const float4 p  = *(const float4*)&Ps[i * PST + f];
            const float4 qv = *(const float4*)&Qs[tid * PST + f];
            const float w0 = p.x + qv.x + r.x + mr.x;
            const float w1 = p.y + qv.y + r.y + mr.y;
            const float w2 = p.z + qv.z + r.z + mr.z;
            const float w3 = p.w + qv.w + r.w + mr.w;
            s += w0 + w1 + w2 + w3;
            ss += w0 * w0 + w1 * w1 + w2 * w2 + w3 * w3;
        }
        const float mu  = s * (1.0f / F_DIM);
        const float var = ss * (1.0f / F_DIM) - mu * mu;
        g_musig[(bn * 64 + i) * 64 + i] = make_float2(mu, rsqrtf(var + EPS_LN));
    }
}

// ---------------------------------------------------------------------------
// Stage 2 (persistent, single-sync pipelined, fp16): grid 304.
// A double-buffered (2x16 KB); P/R/gamma/beta/bias_p in registers.
// One __syncthreads per item.
// ---------------------------------------------------------------------------
#define S2_A0  0
#define S2_A1  16384
#define S2_B   32768
#define S2_VEC 65536
#define SMEM2_BYTES 66048
#define S2_GRID 304

__global__ void __launch_bounds__(256, 2)
hoe_stage2p(const float* __restrict__ gamma,
            const float* __restrict__ beta,
            const float* __restrict__ bias_p,
            const float* __restrict__ b1,
            const float* __restrict__ b2,
            float* __restrict__ out) {
    extern __shared__ char smem[];
    float* b2v = (float*)(smem + S2_VEC);    // 128 (epilogue-indexed, keep smem)

    const uint32_t sbase = cvta_smem(smem);
    const int tid  = threadIdx.x;
    const int lane = tid & 31;
    const int wid  = tid >> 5;
    const int f4   = lane * 4;

    // B slab (32 KB)
    #pragma unroll
    for (int it = 0; it < 8; it++) {
        const int idx = it * 256 + tid;
        cp_async16(sbase + S2_B + idx * 16, g_wsl + idx * 16);
    }
    asm volatile("cp.async.commit_group;" ::: "memory");
    if (tid < 128) b2v[tid] = b2[tid];

    // Constant per-thread vectors (f4 slice)
    const float4 gvv = __ldg((const float4*)(gamma  + f4));
    const float4 bvv = __ldg((const float4*)(beta   + f4));
    const float4 bpv = __ldg((const float4*)(bias_p + f4));
    const float4 b1v = __ldg((const float4*)(b1     + f4));

    const int warpM = wid >> 2;
    const int warpN = wid & 3;
    const int q  = lane >> 3;
    const int lr = lane & 7;
    const int rowA  = lr + ((q & 1) << 3);
    const int cselA = q >> 1;
    uint32_t rowOffA[2];
    #pragma unroll
    for (int mt = 0; mt < 2; mt++)
        rowOffA[mt] = (uint32_t)(warpM * 32 + mt * 16 + rowA) * 256u;
    const int rowB  = lr + ((q >> 1) << 3);
    const int cselB = q & 1;
    uint32_t rowOffB[2];
    #pragma unroll
    for (int np = 0; np < 2; np++)
        rowOffB[np] = (uint32_t)(warpN * 32 + np * 16 + rowB) * 256u;

    float4 q4[8];
    float2 ms[8];
    float4 pp, rr;   // P/R f4-slices (registers; no smem staging)

#define S2_PREFETCH(IT) do {                                                   \
        const int pbn = (IT) >> 6, pi = (IT) & 63;                             \
        const float4 c1 = __ldg((const float4*)(                               \
            g_C + ((pbn * 5 + 1) * M_DIM + pi) * F_DIM + f4));                 \
        const float4 c0 = __ldg((const float4*)(                               \
            g_C + ((pbn * 5 + 0) * M_DIM + pi) * F_DIM + f4));                 \
        const float4 mp = __ldg((const float4*)(                               \
            g_means + (pbn * 2 + 1) * F_DIM + f4));                            \
        const float4 mr = __ldg((const float4*)(                               \
            g_means + (pbn * 2 + 0) * F_DIM + f4));                            \
        pp.x = c1.x + mp.x + b1v.x; pp.y = c1.y + mp.y + b1v.y;                \
        pp.z = c1.z + mp.z + b1v.z; pp.w = c1.w + mp.w + b1v.w;                \
        rr.x = c0.x + mr.x; rr.y = c0.y + mr.y;                                \
        rr.z = c0.z + mr.z; rr.w = c0.w + mr.w;                                \
        const float* Qg = g_C + ((pbn * 5 + 2) * M_DIM) * F_DIM;               \
        const float2* strow = g_musig + (pbn * 64 + pi) * 64;                  \
        _Pragma("unroll")                                                      \
        for (int r = 0; r < 8; r++) {                                          \
            q4[r] = __ldg((const float4*)(Qg + (wid * 8 + r) * F_DIM + f4));   \
            ms[r] = __ldg(&strow[wid * 8 + r]);                                \
        }                                                                      \
    } while (0)

    S2_PREFETCH((int)blockIdx.x);
    asm volatile("cp.async.wait_group 0;" ::: "memory");
    __syncthreads();    // B slab + b2v visible

    uint32_t abuf = S2_A0;
    for (int item = blockIdx.x; item < BN_TOT * M_DIM; item += S2_GRID) {
        const int i = item & 63;

        // --- LN + ReLU + diag bias -> fp16 A slab (buffer abuf) ---
        #pragma unroll
        for (int r = 0; r < 8; r++) {
            const int m = wid * 8 + r;            // j == m
            const bool diag = (m == i);
            float v0 = q4[r].x + pp.x;
            float v1 = q4[r].y + pp.y;
            float v2 = q4[r].z + pp.z;
            float v3 = q4[r].w + pp.w;
            if (diag) { v0 += rr.x; v1 += rr.y; v2 += rr.z; v3 += rr.w; }
            const float mu = ms[r].x, rstd = ms[r].y;
            float h0 = fmaxf(fmaf((v0 - mu) * rstd, gvv.x, bvv.x), 0.f);
            float h1 = fmaxf(fmaf((v1 - mu) * rstd, gvv.y, bvv.y), 0.f);
            float h2 = fmaxf(fmaf((v2 - mu) * rstd, gvv.z, bvv.z), 0.f);
            float h3 = fmaxf(fmaf((v3 - mu) * rstd, gvv.w, bvv.w), 0.f);
            if (diag) { h0 += bpv.x; h1 += bpv.y; h2 += bpv.z; h3 += bpv.w; }
            const uint32_t off = swz((uint32_t)m, (uint32_t)lane * 8u);
            *(uint2*)(smem + abuf + off) = packhf4(h0, h1, h2, h3);
        }
        __syncthreads();   // A[abuf] visible; also orders prior MMA reads of A[abuf^1]

        // --- prefetch next item's vectors (registers only, hidden under MMA) ---
        const int nitem = item + S2_GRID;
        if (nitem < BN_TOT * M_DIM) S2_PREFETCH(nitem);

        // --- MMA: fp16 single-term, 4 ldsm + 8 mma per k-step ---
        float acc[2][4][4];
        #pragma unroll
        for (int mt = 0; mt < 2; mt++)
            #pragma unroll
            for (int nt = 0; nt < 4; nt++)
                #pragma unroll
                for (int e = 0; e < 4; e++) acc[mt][nt][e] = 0.f;

        #pragma unroll
        for (int kk = 0; kk < 8; kk++) {
            const uint32_t kxA = (uint32_t)(((kk << 1) + cselA) ^ lr) << 4;
            const uint32_t kxB = (uint32_t)(((kk << 1) + cselB) ^ lr) << 4;
            uint32_t af[2][4], bf[2][4];
            #pragma unroll
            for (int mt = 0; mt < 2; mt++)
                ldsm4(af[mt], sbase + abuf + rowOffA[mt] + kxA);
            #pragma unroll
            for (int np = 0; np < 2; np++)
                ldsm4(bf[np], sbase + S2_B + rowOffB[np] + kxB);
            #pragma unroll
            for (int mt = 0; mt < 2; mt++)
                #pragma unroll
                for (int nt = 0; nt < 4; nt++) {
                    const int np = nt >> 1;
                    const int hb = (nt & 1) << 1;
                    mma16816h(acc[mt][nt], af[mt], bf[np][hb], bf[np][hb + 1]);
                }
        }

        float* oblk = out + (size_t)item * (M_DIM * D_DIM);
        #pragma unroll
        for (int mt = 0; mt < 2; mt++)
            #pragma unroll
            for (int half = 0; half < 2; half++) {
                const int m = warpM * 32 + mt * 16 + (lane >> 2) + half * 8;
                float* orow = oblk + (size_t)m * 128;
                #pragma unroll
                for (int nt = 0; nt < 4; nt++) {
                    const int n = warpN * 32 + nt * 8 + (lane & 3) * 2;
                    float2 v;
                    v.x = acc[mt][nt][half * 2 + 0] + b2v[n];
                    v.y = acc[mt][nt][half * 2 + 1] + b2v[n + 1];
                    *(float2*)(orow + n) = v;
                }
            }
        abuf ^= (S2_A0 ^ S2_A1);
        // no second sync: next LN writes the other A buffer; the per-item sync
        // above transitively orders all warps' prior MMA reads of that buffer.
    }
#undef S2_PREFETCH
}

// ---------------------------------------------------------------------------
extern "C" void kernel_launch(void* const* d_in, const int* in_sizes, int n_in,
                              void* d_out, int out_size) {
    const float* x      = (const float*)d_in[0];
    const float* W1     = (const float*)d_in[1];
    const float* b1     = (const float*)d_in[2];
    const float* gamma  = (const float*)d_in[3];
    const float* beta   = (const float*)d_in[4];
    const float* bias_p = (const float*)d_in[5];
    const float* W2     = (const float*)d_in[6];
    const float* b2     = (const float*)d_in[7];
    float* out          = (float*)d_out;

    cudaFuncSetAttribute(hoe_stage1mm, cudaFuncAttributeMaxDynamicSharedMemorySize, SMEM1_BYTES);
    cudaFuncSetAttribute(hoe_stats,    cudaFuncAttributeMaxDynamicSharedMemorySize, STATS_SMEM);
    cudaFuncSetAttribute(hoe_stage2p,  cudaFuncAttributeMaxDynamicSharedMemorySize, SMEM2_BYTES);

    hoe_stage1mm<<<dim3(BN_TOT, 4), 256, SMEM1_BYTES>>>(x, W1);
    hoe_stats<<<dim3(BN_TOT, 4), 256, STATS_SMEM>>>(b1, W2);
    hoe_stage2p<<<S2_GRID, 256, SMEM2_BYTES>>>(gamma, beta, bias_p, b1, b2, out);
}

// round 16
// speedup vs baseline: 1.0410x; 1.0410x over previous
#include <cuda_runtime.h>
#include <cuda_fp16.h>
#include <cstdint>

// Shapes (fixed): B=4, N=8, M=64, F=128, D=128
#define BN_TOT 32
#define M_DIM  64
#define F_DIM  128
#define D_DIM  128
#define EPS_LN 1e-5f

// C scratch: [bn][chunk0..2][64 rows][128] fp32.
__device__ float g_C[BN_TOT * 5 * M_DIM * F_DIM];
// colmeans: [bn][0:R-term (chunk3), 1:P-term (chunk4)][128]
__device__ float g_means[BN_TOT * 2 * F_DIM];
// fp16 W2 slab (single term), swizzled layout, 32 KB.
__device__ __align__(16) unsigned char g_wsl[32768];
// Precomputed LN stats per (bn,i,j): {mu, rstd}.
__device__ float2 g_musig[BN_TOT * M_DIM * M_DIM];

// ---------------------------------------------------------------------------
// Helpers
// ---------------------------------------------------------------------------
static __device__ __forceinline__ uint32_t cvta_smem(const void* p) {
    uint32_t a;
    asm("{ .reg .u64 t; cvta.to.shared.u64 t, %1; cvt.u32.u64 %0, t; }"
        : "=r"(a) : "l"(p));
    return a;
}
static __device__ __forceinline__ uint32_t packbf(float lo, float hi) {
    uint32_t r;
    asm("cvt.rn.bf16x2.f32 %0, %1, %2;" : "=r"(r) : "f"(hi), "f"(lo));
    return r;
}
static __device__ __forceinline__ uint32_t swz(uint32_t row, uint32_t kbyte) {
    return row * 256u + ((((kbyte >> 4) ^ (row & 7u)) << 4) | (kbyte & 15u));
}
static __device__ __forceinline__ void ldsm4(uint32_t* r, uint32_t addr) {
    asm volatile("ldmatrix.sync.aligned.m8n8.x4.shared.b16 {%0,%1,%2,%3}, [%4];"
                 : "=r"(r[0]), "=r"(r[1]), "=r"(r[2]), "=r"(r[3]) : "r"(addr));
}
// bf16 mma (stage1)
static __device__ __forceinline__ void mma16816(float* c, const uint32_t* a,
                                                uint32_t b0, uint32_t b1) {
    asm volatile(
        "mma.sync.aligned.m16n8k16.row.col.f32.bf16.bf16.f32 "
        "{%0,%1,%2,%3}, {%4,%5,%6,%7}, {%8,%9}, {%0,%1,%2,%3};"
        : "+f"(c[0]), "+f"(c[1]), "+f"(c[2]), "+f"(c[3])
        : "r"(a[0]), "r"(a[1]), "r"(a[2]), "r"(a[3]), "r"(b0), "r"(b1));
}
// fp16 mma (stage2)
static __device__ __forceinline__ void mma16816h(float* c, const uint32_t* a,
                                                 uint32_t b0, uint32_t b1) {
    asm volatile(
        "mma.sync.aligned.m16n8k16.row.col.f32.f16.f16.f32 "
        "{%0,%1,%2,%3}, {%4,%5,%6,%7}, {%8,%9}, {%0,%1,%2,%3};"
        : "+f"(c[0]), "+f"(c[1]), "+f"(c[2]), "+f"(c[3])
        : "r"(a[0]), "r"(a[1]), "r"(a[2]), "r"(a[3]), "r"(b0), "r"(b1));
}
static __device__ __forceinline__ void cp_async16(uint32_t dst, const void* gp) {
    uint64_t g;
    asm("cvta.to.global.u64 %0, %1;" : "=l"(g) : "l"(gp));
    asm volatile("cp.async.cg.shared.global [%0], [%1], 16;"
                 :: "r"(dst), "l"(g) : "memory");
}
// bf16 hi/lo split (stage1)
static __device__ __forceinline__ void split4(const float4& v, uint2& hi, uint2& lo) {
    const uint32_t hiA = packbf(v.x, v.y);
    const uint32_t hiB = packbf(v.z, v.w);
    const float r0 = v.x - __uint_as_float(hiA << 16);
    const float r1 = v.y - __uint_as_float(hiA & 0xffff0000u);
    const float r2 = v.z - __uint_as_float(hiB << 16);
    const float r3 = v.w - __uint_as_float(hiB & 0xffff0000u);
    hi = make_uint2(hiA, hiB);
    lo = make_uint2(packbf(r0, r1), packbf(r2, r3));
}
static __device__ __forceinline__ uint32_t h2u(__half2 h) {
    return *reinterpret_cast<uint32_t*>(&h);
}
static __device__ __forceinline__ uint2 packhf4(float a, float b, float c, float d) {
    return make_uint2(h2u(__floats2half2_rn(a, b)), h2u(__floats2half2_rn(c, d)));
}

// ---------------------------------------------------------------------------
// Stage 1: grid (32, 4). chunk<3: bf16 3-term MMA C_chunk = x . W1chunk^T.
// chunk==3: light path — mean(x), coalesced smem-staged projections.
// ---------------------------------------------------------------------------
#define S1_AHI 0
#define S1_ALO 16384
#define S1_BHI 32768
#define S1_BLO 65536
#define SMEM1_BYTES 98304
#define WST 132

__global__ void __launch_bounds__(256, 2)
hoe_stage1mm(const float* __restrict__ x, const float* __restrict__ W1) {
    extern __shared__ char smem[];
    const uint32_t sbase = cvta_smem(smem);
    const int tid  = threadIdx.x;
    const int lane = tid & 31;
    const int wid  = tid >> 5;
    const int bn    = blockIdx.x;
    const int chunk = blockIdx.y;

    if (chunk == 3) {
        float* wbuf   = (float*)smem;            // [128][WST]
        float* mean_s = wbuf + 128 * WST;        // 128
        float* part   = mean_s + 128;            // 256
        const float* xb = x + bn * (M_DIM * F_DIM);
        const int f = tid & 127, half = tid >> 7;
        float s = 0.f;
        #pragma unroll 8
        for (int i2 = half * 32; i2 < half * 32 + 32; i2++)
            s += __ldg(xb + i2 * F_DIM + f);
        part[tid] = s;
        __syncthreads();
        if (tid < 128) mean_s[tid] = (part[tid] + part[tid + 128]) * (1.0f / 64.0f);

        #pragma unroll
        for (int sel = 0; sel < 2; sel++) {
            __syncthreads();
            #pragma unroll
            for (int it = 0; it < 16; it++) {
                const int idx = it * 256 + tid;
                const int r = idx >> 5, cw = idx & 31;
                *(float4*)&wbuf[r * WST + cw * 4] =
                    __ldg((const float4*)(W1 + r * 640 + 384 + sel * 128 + cw * 4));
            }
            __syncthreads();
            if (tid < 128) {
                const float* wr = wbuf + tid * WST;
                float a0 = 0.f, a1 = 0.f, a2 = 0.f, a3 = 0.f;
                #pragma unroll 8
                for (int k = 0; k < 128; k += 4) {
                    a0 = fmaf(mean_s[k + 0], wr[k + 0], a0);
                    a1 = fmaf(mean_s[k + 1], wr[k + 1], a1);
                    a2 = fmaf(mean_s[k + 2], wr[k + 2], a2);
                    a3 = fmaf(mean_s[k + 3], wr[k + 3], a3);
                }
                g_means[(bn * 2 + sel) * F_DIM + tid] = (a0 + a1) + (a2 + a3);
            }
        }
        return;
    }

    #pragma unroll
    for (int it = 0; it < 16; it++) {
        const int idx = it * 256 + tid;
        const int r  = idx >> 5;
        const int cw = idx & 31;
        uint2 hi, lo;
        split4(__ldg((const float4*)(W1 + r * 640 + chunk * 128 + cw * 4)), hi, lo);
        const uint32_t off = swz((uint32_t)r, (uint32_t)cw * 8u);
        *(uint2*)(smem + S1_BHI + off) = hi;
        *(uint2*)(smem + S1_BLO + off) = lo;
    }
    const float4* xb = (const float4*)(x + bn * (M_DIM * F_DIM));
    #pragma unroll
    for (int it = 0; it < 8; it++) {
        const int e   = it * 256 + tid;
        const int row = e >> 5;
        const int cw  = e & 31;
        uint2 hi, lo;
        split4(__ldg(xb + e), hi, lo);
        const uint32_t off = swz((uint32_t)row, (uint32_t)cw * 8u);
        *(uint2*)(smem + S1_AHI + off) = hi;
        *(uint2*)(smem + S1_ALO + off) = lo;
    }
    __syncthreads();

    const int warpM = wid >> 2;
    const int warpN = wid & 3;
    const int q  = lane >> 3;
    const int lr = lane & 7;
    const int rowA  = lr + ((q & 1) << 3);
    const int cselA = q >> 1;
    uint32_t rowOffA[2];
    #pragma unroll
    for (int mt = 0; mt < 2; mt++)
        rowOffA[mt] = (uint32_t)(warpM * 32 + mt * 16 + rowA) * 256u;
    const int rowB  = lr + ((q >> 1) << 3);
    const int cselB = q & 1;
    uint32_t rowOffB[2];
    #pragma unroll
    for (int np = 0; np < 2; np++)
        rowOffB[np] = (uint32_t)(warpN * 32 + np * 16 + rowB) * 256u;

    float acc[2][4][4];
    #pragma unroll
    for (int mt = 0; mt < 2; mt++)
        #pragma unroll
        for (int nt = 0; nt < 4; nt++)
            #pragma unroll
            for (int e = 0; e < 4; e++) acc[mt][nt][e] = 0.f;

    #pragma unroll
    for (int kk = 0; kk < 8; kk++) {
        const uint32_t kxA = (uint32_t)(((kk << 1) + cselA) ^ lr) << 4;
        const uint32_t kxB = (uint32_t)(((kk << 1) + cselB) ^ lr) << 4;
        uint32_t ah[2][4], al[2][4], bh[2][4], bl[2][4];
        #pragma unroll
        for (int mt = 0; mt < 2; mt++) {
            ldsm4(ah[mt], sbase + S1_AHI + rowOffA[mt] + kxA);
            ldsm4(al[mt], sbase + S1_ALO + rowOffA[mt] + kxA);
        }
        #pragma unroll
        for (int np = 0; np < 2; np++) {
            ldsm4(bh[np], sbase + S1_BHI + rowOffB[np] + kxB);
            ldsm4(bl[np], sbase + S1_BLO + rowOffB[np] + kxB);
        }
        #pragma unroll
        for (int mt = 0; mt < 2; mt++)
            #pragma unroll
            for (int nt = 0; nt < 4; nt++) {
                const int np = nt >> 1;
                const int hb = (nt & 1) << 1;
                mma16816(acc[mt][nt], ah[mt], bh[np][hb], bh[np][hb + 1]);
                mma16816(acc[mt][nt], al[mt], bh[np][hb], bh[np][hb + 1]);
                mma16816(acc[mt][nt], ah[mt], bl[np][hb], bl[np][hb + 1]);
            }
    }

    float* cb = g_C + ((bn * 5 + chunk) * M_DIM) * F_DIM;
    #pragma unroll
    for (int mt = 0; mt < 2; mt++)
        #pragma unroll
        for (int half = 0; half < 2; half++) {
            const int m = warpM * 32 + mt * 16 + (lane >> 2) + half * 8;
            #pragma unroll
            for (int nt = 0; nt < 4; nt++) {
                const int n = warpN * 32 + nt * 8 + (lane & 3) * 2;
                *(float2*)(cb + m * 128 + n) =
                    make_float2(acc[mt][nt][half * 2], acc[mt][nt][half * 2 + 1]);
            }
        }
}

// ---------------------------------------------------------------------------
// Stats (+ fp16 W2 prep folded in): grid (32 bn, 4 j-slices) = 128 blocks.
// Cross-GEMM mapping: i in {lane, lane+32} (4-way conflicts), jj in
// {warp, warp+8} (warp-uniform broadcast, conflict-free).
// ---------------------------------------------------------------------------
#define PST 132
#define STATS_SMEM ((64 * PST + 16 * PST + 160) * 4)

__global__ void __launch_bounds__(256, 1)
hoe_stats(const float* __restrict__ b1, const float* __restrict__ W2) {
    extern __shared__ float sf[];
    float* Ps   = sf;                  // [64][PST]
    float* Qs   = Ps + 64 * PST;       // [16][PST]
    float* sumP = Qs + 16 * PST;       // 64
    float* sqP  = sumP + 64;           // 64
    float* sumQ = sqP + 64;            // 16
    float* sqQ  = sumQ + 16;           // 16

    const int bn  = blockIdx.x;
    const int j0  = blockIdx.y * 16;
    const int tid = threadIdx.x;

    // --- folded W2 prep (single fp16 term) ---
    {
        const int lb = blockIdx.x * 4 + blockIdx.y;
        if (tid < 32) {
            const int idx = lb * 32 + tid;        // < 4096
            const int r = idx >> 5, cw = idx & 31;
            const float4 v = __ldg((const float4*)(W2 + r * 128 + cw * 4));
            const uint32_t off = swz((uint32_t)r, (uint32_t)cw * 8u);
            *(uint2*)(g_wsl + off) = packhf4(v.x, v.y, v.z, v.w);
        }
    }

    const float* C0 = g_C + ((bn * 5 + 0) * M_DIM) * F_DIM;
    const float* C1 = g_C + ((bn * 5 + 1) * M_DIM) * F_DIM;
    const float* C2 = g_C + ((bn * 5 + 2) * M_DIM) * F_DIM;
    const float* mR = g_means + (bn * 2 + 0) * F_DIM;
    const float* mP = g_means + (bn * 2 + 1) * F_DIM;

    #pragma unroll
    for (int it = 0; it < 8; it++) {
        const int e = it * 256 + tid;
        const int i = e >> 5;
        const int f = (e & 31) * 4;
        float4 p = __ldg((const float4*)(C1 + i * 128 + f));
        const float4 mp = __ldg((const float4*)(mP + f));
        const float4 bb = __ldg((const float4*)(b1 + f));
        p.x += mp.x + bb.x; p.y += mp.y + bb.y;
        p.z += mp.z + bb.z; p.w += mp.w + bb.w;
        *(float4*)&Ps[i * PST + f] = p;
    }
    #pragma unroll
    for (int it = 0; it < 2; it++) {
        const int e = it * 256 + tid;
        const int jj = e >> 5;
        const int f  = (e & 31) * 4;
        *(float4*)&Qs[jj * PST + f] = __ldg((const float4*)(C2 + (j0 + jj) * 128 + f));
    }
    __syncthreads();

    {
        const int i = tid >> 2, part = tid & 3;
        float s = 0.f, ss = 0.f;
        #pragma unroll
        for (int f = part * 32; f < part * 32 + 32; f += 4) {
            const float4 p = *(const float4*)&Ps[i * PST + f];
            s += p.x + p.y + p.z + p.w;
            ss += p.x * p.x + p.y * p.y + p.z * p.z + p.w * p.w;
        }
        s  += __shfl_xor_sync(0xffffffffu, s, 1);  s  += __shfl_xor_sync(0xffffffffu, s, 2);
        ss += __shfl_xor_sync(0xffffffffu, ss, 1); ss += __shfl_xor_sync(0xffffffffu, ss, 2);
        if (part == 0) { sumP[i] = s; sqP[i] = ss; }
    }
    if (tid < 64) {
        const int jj = tid >> 2, part = tid & 3;
        float s = 0.f, ss = 0.f;
        #pragma unroll
        for (int f = part * 32; f < part * 32 + 32; f += 4) {
            const float4 p = *(const float4*)&Qs[jj * PST + f];
            s += p.x + p.y + p.z + p.w;
            ss += p.x * p.x + p.y * p.y + p.z * p.z + p.w * p.w;
        }
        s  += __shfl_xor_sync(0xffffffffu, s, 1);  s  += __shfl_xor_sync(0xffffffffu, s, 2);
        ss += __shfl_xor_sync(0xffffffffu, ss, 1); ss += __shfl_xor_sync(0xffffffffu, ss, 2);
        if (part == 0) { sumQ[jj] = s; sqQ[jj] = ss; }
    }
    __syncthreads();

    {
        const int lane = tid & 31;
        const int wq   = tid >> 5;      // 0..7
        float a00 = 0, a01 = 0, a10 = 0, a11 = 0;
        #pragma unroll 8
        for (int f = 0; f < 128; f += 4) {
            const float4 p0 = *(const float4*)&Ps[lane * PST + f];
            const float4 p1 = *(const float4*)&Ps[(lane + 32) * PST + f];
            const float4 q0 = *(const float4*)&Qs[wq * PST + f];
            const float4 q1 = *(const float4*)&Qs[(wq + 8) * PST + f];
            a00 = fmaf(p0.x, q0.x, a00); a00 = fmaf(p0.y, q0.y, a00);
            a00 = fmaf(p0.z, q0.z, a00); a00 = fmaf(p0.w, q0.w, a00);
            a01 = fmaf(p0.x, q1.x, a01); a01 = fmaf(p0.y, q1.y, a01);
            a01 = fmaf(p0.z, q1.z, a01); a01 = fmaf(p0.w, q1.w, a01);
            a10 = fmaf(p1.x, q0.x, a10); a10 = fmaf(p1.y, q0.y, a10);
            a10 = fmaf(p1.z, q0.z, a10); a10 = fmaf(p1.w, q0.w, a10);
            a11 = fmaf(p1.x, q1.x, a11); a11 = fmaf(p1.y, q1.y, a11);
            a11 = fmaf(p1.z, q1.z, a11); a11 = fmaf(p1.w, q1.w, a11);
        }
        const float cr[2][2] = { { a00, a01 }, { a10, a11 } };
        #pragma unroll
        for (int a = 0; a < 2; a++) {
            const int i = lane + a * 32;
            #pragma unroll
            for (int b = 0; b < 2; b++) {
                const int jj = wq + b * 8;
                const int j  = j0 + jj;
                if (i == j) continue;
                const float s   = sumP[i] + sumQ[jj];
                const float ss  = sqP[i] + 2.f * cr[a][b] + sqQ[jj];
                const float mu  = s * (1.0f / F_DIM);
                const float var = ss * (1.0f / F_DIM) - mu * mu;
                g_musig[(bn * 64 + i) * 64 + j] = make_float2(mu, rsqrtf(var + EPS_LN));
            }
        }
    }

    if (tid < 16) {
        const int i = j0 + tid;
        float s = 0.f, ss = 0.f;
        #pragma unroll 8
        for (int f = 0; f < 128; f += 4) {
            const float4 r  = __ldg((const float4*)(C0 + i * 128 + f));
            const float4 mr = __ldg((const float4*)(mR + f));
            const float4 p  = *(const float4*)&Ps[i * PST + f];
            const float4 qv = *(const float4*)&Qs[tid * PST + f];
            const float w0 = p.x + qv.x + r.x + mr.x;
            const float w1 = p.y + qv.y + r.y + mr.y;
            const float w2 = p.z + qv.z + r.z + mr.z;
            const float w3 = p.w + qv.w + r.w + mr.w;
            s += w0 + w1 + w2 + w3;
            ss += w0 * w0 + w1 * w1 + w2 * w2 + w3 * w3;
        }
        const float mu  = s * (1.0f / F_DIM);
        const float var = ss * (1.0f / F_DIM) - mu * mu;
        g_musig[(bn * 64 + i) * 64 + i] = make_float2(mu, rsqrtf(var + EPS_LN));
    }
}

// ---------------------------------------------------------------------------
// Stage 2 (persistent, pipelined, fp16 single-term): grid 304.
// EXACT R13 structure (two syncs per item, smem Pv/Rv, 122 regs, no spills).
// ---------------------------------------------------------------------------
#define S2_A   0
#define S2_B   16384
#define S2_VEC 49152
#define SMEM2_BYTES 53248
#define S2_GRID 304

__global__ void __launch_bounds__(256, 2)
hoe_stage2p(const float* __restrict__ gamma,
            const float* __restrict__ beta,
            const float* __restrict__ bias_p,
            const float* __restrict__ b1,
            const float* __restrict__ b2,
            float* __restrict__ out) {
    extern __shared__ char smem[];
    float* Pv  = (float*)(smem + S2_VEC);    // [2][128]
    float* Rv  = Pv + 256;                   // [2][128]
    float* gv  = Rv + 256;
    float* bv  = gv + 128;
    float* bpv = bv + 128;
    float* b2v = bpv + 128;

    const uint32_t sbase = cvta_smem(smem);
    const int tid  = threadIdx.x;
    const int lane = tid & 31;
    const int wid  = tid >> 5;
    const int f4   = lane * 4;

    // B slab (32 KB)
    #pragma unroll
    for (int it = 0; it < 8; it++) {
        const int idx = it * 256 + tid;
        cp_async16(sbase + S2_B + idx * 16, g_wsl + idx * 16);
    }
    asm volatile("cp.async.commit_group;" ::: "memory");
    if (tid < 128) {
        gv[tid]  = gamma[tid];
        bv[tid]  = beta[tid];
        bpv[tid] = bias_p[tid];
        b2v[tid] = b2[tid];
    }

    const int warpM = wid >> 2;
    const int warpN = wid & 3;
    const int q  = lane >> 3;
    const int lr = lane & 7;
    const int rowA  = lr + ((q & 1) << 3);
    const int cselA = q >> 1;
    uint32_t rowOffA[2];
    #pragma unroll
    for (int mt = 0; mt < 2; mt++)
        rowOffA[mt] = (uint32_t)(warpM * 32 + mt * 16 + rowA) * 256u;
    const int rowB  = lr + ((q >> 1) << 3);
    const int cselB = q & 1;
    uint32_t rowOffB[2];
    #pragma unroll
    for (int np = 0; np < 2; np++)
        rowOffB[np] = (uint32_t)(warpN * 32 + np * 16 + rowB) * 256u;

    float4 q4[8];
    float2 ms[8];

#define S2_PREFETCH(IT, BUF) do {                                              \
        const int pbn = (IT) >> 6, pi = (IT) & 63;                             \
        if (tid < 128) {                                                       \
            Pv[(BUF) * 128 + tid] =                                            \
                g_C[((pbn * 5 + 1) * M_DIM + pi) * F_DIM + tid]                \
                + g_means[(pbn * 2 + 1) * F_DIM + tid] + b1[tid];              \
            Rv[(BUF) * 128 + tid] =                                            \
                g_C[((pbn * 5 + 0) * M_DIM + pi) * F_DIM + tid]                \
                + g_means[(pbn * 2 + 0) * F_DIM + tid];                        \
        }                                                                      \
        const float* Qg = g_C + ((pbn * 5 + 2) * M_DIM) * F_DIM;               \
        const float2* strow = g_musig + (pbn * 64 + pi) * 64;                  \
        _Pragma("unroll")                                                      \
        for (int r = 0; r < 8; r++) {                                          \
            q4[r] = __ldg((const float4*)(Qg + (wid * 8 + r) * F_DIM + f4));   \
            ms[r] = __ldg(&strow[wid * 8 + r]);                                \
        }                                                                      \
    } while (0)

    S2_PREFETCH((int)blockIdx.x, 0);
    asm volatile("cp.async.wait_group 0;" ::: "memory");
    __syncthreads();

    int p = 0;
    for (int item = blockIdx.x; item < BN_TOT * M_DIM; item += S2_GRID) {
        const int i = item & 63;
        const float* Pb = Pv + p * 128;
        const float* Rb = Rv + p * 128;

        // --- LN + ReLU + diag bias -> fp16 A slab ---
        const float pv0 = Pb[f4], pv1 = Pb[f4 + 1], pv2 = Pb[f4 + 2], pv3 = Pb[f4 + 3];
        #pragma unroll
        for (int r = 0; r < 8; r++) {
            const int m = wid * 8 + r;            // j == m
            const bool diag = (m == i);
            float v0 = q4[r].x + pv0;
            float v1 = q4[r].y + pv1;
            float v2 = q4[r].z + pv2;
            float v3 = q4[r].w + pv3;
            if (diag) {
                v0 += Rb[f4 + 0]; v1 += Rb[f4 + 1];
                v2 += Rb[f4 + 2]; v3 += Rb[f4 + 3];
            }
            const float mu = ms[r].x, rstd = ms[r].y;
            float h0 = fmaxf(fmaf((v0 - mu) * rstd, gv[f4 + 0], bv[f4 + 0]), 0.f);
            float h1 = fmaxf(fmaf((v1 - mu) * rstd, gv[f4 + 1], bv[f4 + 1]), 0.f);
            float h2 = fmaxf(fmaf((v2 - mu) * rstd, gv[f4 + 2], bv[f4 + 2]), 0.f);
            float h3 = fmaxf(fmaf((v3 - mu) * rstd, gv[f4 + 3], bv[f4 + 3]), 0.f);
            if (diag) {
                h0 += bpv[f4 + 0]; h1 += bpv[f4 + 1];
                h2 += bpv[f4 + 2]; h3 += bpv[f4 + 3];
            }
            const uint32_t off = swz((uint32_t)m, (uint32_t)lane * 8u);
            *(uint2*)(smem + S2_A + off) = packhf4(h0, h1, h2, h3);
        }
        __syncthreads();

        const int nitem = item + S2_GRID;
        if (nitem < BN_TOT * M_DIM) S2_PREFETCH(nitem, p ^ 1);

        // --- MMA: fp16 single-term, 4 ldsm + 8 mma per k-step ---
        float acc[2][4][4];
        #pragma unroll
        for (int mt = 0; mt < 2; mt++)
            #pragma unroll
            for (int nt = 0; nt < 4; nt++)
                #pragma unroll
                for (int e = 0; e < 4; e++) acc[mt][nt][e] = 0.f;

        #pragma unroll
        for (int kk = 0; kk < 8; kk++) {
            const uint32_t kxA = (uint32_t)(((kk << 1) + cselA) ^ lr) << 4;
            const uint32_t kxB = (uint32_t)(((kk << 1) + cselB) ^ lr) << 4;
            uint32_t af[2][4], bf[2][4];
            #pragma unroll
            for (int mt = 0; mt < 2; mt++)
                ldsm4(af[mt], sbase + S2_A + rowOffA[mt] + kxA);
            #pragma unroll
            for (int np = 0; np < 2; np++)
                ldsm4(bf[np], sbase + S2_B + rowOffB[np] + kxB);
            #pragma unroll
            for (int mt = 0; mt < 2; mt++)
                #pragma unroll
                for (int nt = 0; nt < 4; nt++) {
                    const int np = nt >> 1;
                    const int hb = (nt & 1) << 1;
                    mma16816h(acc[mt][nt], af[mt], bf[np][hb], bf[np][hb + 1]);
                }
        }

        float* oblk = out + (size_t)item * (M_DIM * D_DIM);
        #pragma unroll
        for (int mt = 0; mt < 2; mt++)
            #pragma unroll
            for (int half = 0; half < 2; half++) {
                const int m = warpM * 32 + mt * 16 + (lane >> 2) + half * 8;
                float* orow = oblk + (size_t)m * 128;
                #pragma unroll
                for (int nt = 0; nt < 4; nt++) {
                    const int n = warpN * 32 + nt * 8 + (lane & 3) * 2;
                    float2 v;
                    v.x = acc[mt][nt][half * 2 + 0] + b2v[n];
                    v.y = acc[mt][nt][half * 2 + 1] + b2v[n + 1];
                    *(float2*)(orow + n) = v;
                }
            }
        __syncthreads();
        p ^= 1;
    }
#undef S2_PREFETCH
}

// ---------------------------------------------------------------------------
extern "C" void kernel_launch(void* const* d_in, const int* in_sizes, int n_in,
                              void* d_out, int out_size) {
    const float* x      = (const float*)d_in[0];
    const float* W1     = (const float*)d_in[1];
    const float* b1     = (const float*)d_in[2];
    const float* gamma  = (const float*)d_in[3];
    const float* beta   = (const float*)d_in[4];
    const float* bias_p = (const float*)d_in[5];
    const float* W2     = (const float*)d_in[6];
    const float* b2     = (const float*)d_in[7];
    float* out          = (float*)d_out;

    cudaFuncSetAttribute(hoe_stage1mm, cudaFuncAttributeMaxDynamicSharedMemorySize, SMEM1_BYTES);
    cudaFuncSetAttribute(hoe_stats,    cudaFuncAttributeMaxDynamicSharedMemorySize, STATS_SMEM);
    cudaFuncSetAttribute(hoe_stage2p,  cudaFuncAttributeMaxDynamicSharedMemorySize, SMEM2_BYTES);

    hoe_stage1mm<<<dim3(BN_TOT, 4), 256, SMEM1_BYTES>>>(x, W1);
    hoe_stats<<<dim3(BN_TOT, 4), 256, STATS_SMEM>>>(b1, W2);
    hoe_stage2p<<<S2_GRID, 256, SMEM2_BYTES>>>(gamma, beta, bias_p, b1, b2, out);
}